// round 12
// baseline (speedup 1.0000x reference)
#include <cuda_runtime.h>
#include <cuda_bf16.h>
#include <cstdint>

// ============================================================================
// CustomConvLayer: 9 bilinear taps @ integer+0.4 == exact 4x4 conv (folded).
// HMMA (mma.sync m16n8k16 bf16) implicit GEMM, bf16x3 split for fp32 accuracy.
// R9: (1) single merged prep kernel writing the permuted B-fragment layout
//     directly; (2) register-prefetch pipeline: next chunk's patch LDGs issue
//     at tap 0 and are consumed at chunk end, hiding global latency under the
//     16-tap MMA stream.
//   x: [8,64,128,128] f32   w: [64,64,9] f32   taps: [9,2] f32
//   out: [8,64,128,128] f32
// ============================================================================

#define B_    8
#define CIN   64
#define COUT  64
#define HW    128
#define NTAP  9

// pixel tile per CTA: 8 (y) x 16 (x); patch 11 x 19 pixels
#define TY 8
#define TX 16
#define IY 11
#define IX 19
#define NPX (IY * IX)            // 209
#define PITCH 48                 // bytes per pixel row (16 bf16 = 32B, padded)
#define PHALF (NPX * PITCH)      // 10032 B per half (hi / lo)
#define STAGE_N (16 * NPX)       // 3344 elements per chunk

// permuted per-lane fragments: [tap][chunk][nh][part(4)][lane(32)] of uint4
//  part0/1 = hi (nb 0,1 / nb 2,3), part2/3 = lo
__device__ uint4 g_wperm[16 * 4 * 2 * 4 * 32];   // 256 KB

// ---------------------------------------------------------------------------
// Merged prep: fold 9 taps -> 4x4, bf16 hi/lo split, scatter directly into
// the per-lane fragment layout consumed by load_b (validated in R8).
//   For weight element (tap, o, i):
//     nh=o/32, nb=(o%32)/8, g=o%8 ; chunk=i/16, r=i%16, reg=r/8,
//     tig=(r%8)/2, byte=r%2, lane=g*4+tig, comp=(nb&1)*2+reg
//     hi -> part nb/2, lo -> part 2+nb/2
// ---------------------------------------------------------------------------
__global__ void prep_kernel(const float* __restrict__ w,
                            const float* __restrict__ off) {
    int idx = blockIdx.x * blockDim.x + threadIdx.x;
    if (idx >= COUT * CIN) return;
    int o = idx >> 6, i = idx & 63;
    float acc[16];
#pragma unroll
    for (int t = 0; t < 16; t++) acc[t] = 0.f;
#pragma unroll
    for (int k = 0; k < NTAP; k++) {
        float dy = off[2 * k + 0];
        float dx = off[2 * k + 1];
        float fyf = floorf(dy), fxf = floorf(dx);
        int iy = (int)fyf, ix = (int)fxf;
        float fy = dy - fyf, fx = dx - fxf;
        float wk = w[(o * CIN + i) * NTAP + k];
        acc[iy * 4 + ix]           += wk * (1.f - fy) * (1.f - fx);
        acc[iy * 4 + ix + 1]       += wk * (1.f - fy) * fx;
        acc[(iy + 1) * 4 + ix]     += wk * fy * (1.f - fx);
        acc[(iy + 1) * 4 + ix + 1] += wk * fy * fx;
    }
    const int nh = o >> 5, nb = (o >> 3) & 3, g = o & 7;
    const int chunk = i >> 4, r = i & 15;
    const int reg = (r >> 3) & 1, tig = (r & 7) >> 1, byt = r & 1;
    const int lane = g * 4 + tig;
    const int comp = (nb & 1) * 2 + reg;
    __nv_bfloat16* wp = (__nv_bfloat16*)g_wperm;
#pragma unroll
    for (int t = 0; t < 16; t++) {
        float v = acc[t];
        __nv_bfloat16 h = __float2bfloat16(v);
        __nv_bfloat16 l = __float2bfloat16(v - __bfloat162float(h));
        size_t slab = (size_t)((t * 4 + chunk) * 2 + nh) * 4;
        wp[((slab + (nb >> 1)) * 32 + lane) * 8 + comp * 2 + byt]     = h;
        wp[((slab + 2 + (nb >> 1)) * 32 + lane) * 8 + comp * 2 + byt] = l;
    }
}

// ---------------------------------------------------------------------------
__device__ __forceinline__ uint32_t smem_to_u32(const void* p) {
    uint32_t a;
    asm("{ .reg .u64 t; cvta.to.shared.u64 t, %1; cvt.u32.u64 %0, t; }"
        : "=r"(a) : "l"(p));
    return a;
}

#define LDSM4(r, addr) \
    asm volatile("ldmatrix.sync.aligned.m8n8.x4.shared.b16 {%0,%1,%2,%3}, [%4];" \
                 : "=r"((r)[0]), "=r"((r)[1]), "=r"((r)[2]), "=r"((r)[3]) \
                 : "r"(addr))

#define MMA16816(c, a, bb) \
    asm("mma.sync.aligned.m16n8k16.row.col.f32.bf16.bf16.f32 " \
        "{%0,%1,%2,%3}, {%4,%5,%6,%7}, {%8,%9}, {%0,%1,%2,%3};" \
        : "+f"((c)[0]), "+f"((c)[1]), "+f"((c)[2]), "+f"((c)[3]) \
        : "r"((a)[0]), "r"((a)[1]), "r"((a)[2]), "r"((a)[3]), \
          "r"((bb)[0]), "r"((bb)[1]))

// coalesced B load: 4 x LDG.128 per (tap, chunk)
__device__ __forceinline__ void load_b(const uint4* wp,
                                       uint32_t bh[4][2], uint32_t bl[4][2]) {
    uint4 h0 = wp[0], h1 = wp[32], l0 = wp[64], l1 = wp[96];
    bh[0][0] = h0.x; bh[0][1] = h0.y; bh[1][0] = h0.z; bh[1][1] = h0.w;
    bh[2][0] = h1.x; bh[2][1] = h1.y; bh[3][0] = h1.z; bh[3][1] = h1.w;
    bl[0][0] = l0.x; bl[0][1] = l0.y; bl[1][0] = l0.z; bl[1][1] = l0.w;
    bl[2][0] = l1.x; bl[2][1] = l1.y; bl[3][0] = l1.z; bl[3][1] = l1.w;
}

// ---------------------------------------------------------------------------
// 256 threads, 8 warps. Warp w: y rows {2*(w%4), 2*(w%4)+1}, couts (w/4)*32..+31.
// ---------------------------------------------------------------------------
__global__ __launch_bounds__(256, 2)
void conv_hmma_kernel(const float* __restrict__ x, float* __restrict__ out) {
    __shared__ __align__(16) char patch[2 * PHALF];   // hi then lo, 20064 B

    const int tid  = threadIdx.x;
    const int lane = tid & 31;
    const int w    = tid >> 5;
    const int wy   = w & 3;                 // y-pair index
    const int nh   = w >> 2;                // cout half
    const int nbase = nh * 32;
    const int g   = lane >> 2;
    const int tig = lane & 3;

    const int b  = blockIdx.z;
    const int y0 = blockIdx.y * TY;
    const int x0 = blockIdx.x * TX;

    const uint32_t sbase = smem_to_u32(patch);
    const uint32_t laneoff =
        (uint32_t)(((lane & 7) + ((lane >> 3) & 1) * 8) * PITCH + (lane >> 4) * 16);

    float acc[2][4][4];
#pragma unroll
    for (int m = 0; m < 2; m++)
#pragma unroll
        for (int nb = 0; nb < 4; nb++)
#pragma unroll
            for (int q = 0; q < 4; q++) acc[m][nb][q] = 0.f;

    const float* xb = x + (size_t)b * CIN * HW * HW;

    // ---- initial stage: chunk 0 (LDG -> cvt -> STS) ----
    for (int idx = tid; idx < STAGE_N; idx += 256) {
        int cl = idx / NPX;
        int px = idx - cl * NPX;
        int py = px / IX, pxx = px - py * IX;
        int gy = y0 + py - 1, gx = x0 + pxx - 1;
        float v = 0.f;
        if ((unsigned)gy < (unsigned)HW && (unsigned)gx < (unsigned)HW)
            v = xb[((size_t)cl * HW + gy) * HW + gx];
        __nv_bfloat16 h = __float2bfloat16(v);
        __nv_bfloat16 l = __float2bfloat16(v - __bfloat162float(h));
        *(__nv_bfloat16*)(patch + px * PITCH + cl * 2) = h;
        *(__nv_bfloat16*)(patch + PHALF + px * PITCH + cl * 2) = l;
    }
    __syncthreads();

    float pf[14];

    for (int chunk = 0; chunk < 4; chunk++) {
        const uint4* wp0 =
            g_wperm + (((0 * 4 + chunk) * 2 + nh) * 4) * 32 + lane;
        #define TAPSTRIDE 1024   // uint4 stride between taps

        uint32_t bh[2][4][2], bl[2][4][2];
        load_b(wp0, bh[0], bl[0]);

#pragma unroll
        for (int tap = 0; tap < 16; tap++) {
            const int cur = tap & 1;
            if (tap < 15)
                load_b(wp0 + (tap + 1) * TAPSTRIDE, bh[cur ^ 1], bl[cur ^ 1]);

            if (tap == 0 && chunk < 3) {
                // prefetch next chunk's patch into registers; latency hidden
                // under this chunk's entire MMA stream
#pragma unroll
                for (int j = 0; j < 14; j++) {
                    int idx = tid + j * 256;
                    float v = 0.f;
                    if (idx < STAGE_N) {
                        int cl = idx / NPX;
                        int px = idx - cl * NPX;
                        int py = px / IX, pxx = px - py * IX;
                        int gy = y0 + py - 1, gx = x0 + pxx - 1;
                        if ((unsigned)gy < (unsigned)HW &&
                            (unsigned)gx < (unsigned)HW)
                            v = xb[((size_t)((chunk + 1) * 16 + cl) * HW + gy) *
                                       HW + gx];
                    }
                    pf[j] = v;
                }
            }

            const int dy = tap >> 2, dx = tap & 3;
#pragma unroll
            for (int m = 0; m < 2; m++) {
                const int sy = wy * 2 + m + dy;
                const uint32_t abase =
                    sbase + (uint32_t)((sy * IX + dx) * PITCH) + laneoff;
                uint32_t ah[4], al[4];
                LDSM4(ah, abase);
                LDSM4(al, abase + PHALF);
#pragma unroll
                for (int nb = 0; nb < 4; nb++) {
                    MMA16816(acc[m][nb], ah, bh[cur][nb]);
                    MMA16816(acc[m][nb], ah, bl[cur][nb]);
                    MMA16816(acc[m][nb], al, bh[cur][nb]);
                }
            }
        }

        if (chunk < 3) {
            __syncthreads();   // all warps done reading current patch
#pragma unroll
            for (int j = 0; j < 14; j++) {
                int idx = tid + j * 256;
                if (idx < STAGE_N) {
                    int px = idx % NPX;
                    int cl = idx / NPX;
                    float v = pf[j];
                    __nv_bfloat16 h = __float2bfloat16(v);
                    __nv_bfloat16 l = __float2bfloat16(v - __bfloat162float(h));
                    *(__nv_bfloat16*)(patch + px * PITCH + cl * 2) = h;
                    *(__nv_bfloat16*)(patch + PHALF + px * PITCH + cl * 2) = l;
                }
            }
            __syncthreads();
        }
    }

    // ---- epilogue ----
    // c-frag: c0 = (x=g,   cout=tig*2), c1 = (x=g,   cout=tig*2+1)
    //         c2 = (x=g+8, cout=tig*2), c3 = (x=g+8, cout=tig*2+1)
#pragma unroll
    for (int m = 0; m < 2; m++) {
        const int gy = y0 + wy * 2 + m;
#pragma unroll
        for (int nb = 0; nb < 4; nb++) {
            const int n = nbase + nb * 8 + tig * 2;
            float* o0 = out + ((size_t)b * COUT + n) * (HW * HW) + (size_t)gy * HW;
            float* o1 = o0 + (size_t)(HW * HW);
            o0[x0 + g]     = acc[m][nb][0];
            o1[x0 + g]     = acc[m][nb][1];
            o0[x0 + g + 8] = acc[m][nb][2];
            o1[x0 + g + 8] = acc[m][nb][3];
        }
    }
}

extern "C" void kernel_launch(void* const* d_in, const int* in_sizes, int n_in,
                              void* d_out, int out_size) {
    const float* x   = (const float*)d_in[0];
    const float* w   = (const float*)d_in[1];
    const float* off = (const float*)d_in[2];
    float* out = (float*)d_out;

    prep_kernel<<<(COUT * CIN + 255) / 256, 256>>>(w, off);

    dim3 grid(HW / TX, HW / TY, B_);   // (8, 16, 8) = 1024 CTAs
    conv_hmma_kernel<<<grid, 256>>>(x, out);
}